// round 2
// baseline (speedup 1.0000x reference)
#include <cuda_runtime.h>
#include <math.h>

// Problem constants
#define B 512
#define S 16
#define H 501
#define C 7
#define KP 512          // padded K (inner dim)
#define DEP_OFF 0
#define ENC_OFF (B*S*S) // 131072

// ---------------- device state ----------------
__device__ float g_gs  [B][KP];        // graph state (padded, tail zeros)
__device__ float g_hin [B][KP];        // h_in buffer (padded, tail zeros)
__device__ float g_zpad[B][KP];        // padded z
__device__ float g_WcatT[KP][1024];    // B matrix for K1: [k][2h+e], e=0 gate, e=1 map
__device__ float g_Whh3T[KP][1536];    // B matrix for K2: [k][3h+j], j=r,z,n
__device__ float g_WlinT[KP][KP];      // W_lin1^T padded
__device__ float g_f0[KP];             // sigmoid(b_gate)*b_map
__device__ int   g_cls[B*S];           // argmax of one-hot node encoding
__device__ float g_d[B][S];            // cached dots nhs[j]·we2
__device__ float g_aprev[B];           // cached dot hv·we1

__device__ __forceinline__ float sigm(float x){ return 1.0f/(1.0f+expf(-x)); }

// ---------------- init: transpose/interleave weights, pad z, f0, classes ----------------
__global__ void kinit(const float* __restrict__ Wg, const float* __restrict__ Wm,
                      const float* __restrict__ Whh, const float* __restrict__ Wlin,
                      const float* __restrict__ bgate, const float* __restrict__ bmap,
                      const float* __restrict__ z, const float* __restrict__ ne)
{
    int gt = blockIdx.x*blockDim.x + threadIdx.x;
    int gstep = gridDim.x*blockDim.x;
    // WcatT
    for (int i=gt; i<KP*1024; i+=gstep){
        int k = i>>10, n = i & 1023; int h = n>>1, e = n&1;
        float v = 0.f;
        if (k<H && h<H) v = e ? Wm[h*H+k] : Wg[h*H+k];
        (&g_WcatT[0][0])[i] = v;
    }
    // Whh3T
    for (int i=gt; i<KP*1536; i+=gstep){
        int k = i/1536, n = i%1536; int h = n/3, j = n%3;
        float v = 0.f;
        if (k<H && h<H) v = Whh[(j*H+h)*H + k];
        (&g_Whh3T[0][0])[i] = v;
    }
    // WlinT
    for (int i=gt; i<KP*KP; i+=gstep){
        int k = i>>9, h = i & 511;
        float v = 0.f;
        if (k<H && h<H) v = Wlin[h*H+k];
        (&g_WlinT[0][0])[i] = v;
    }
    // zpad
    for (int i=gt; i<B*KP; i+=gstep){
        int b = i>>9, k = i & 511;
        (&g_zpad[0][0])[i] = (k<H) ? z[b*H+k] : 0.f;
    }
    // f0
    for (int i=gt; i<KP; i+=gstep){
        g_f0[i] = (i<H) ? sigm(bgate[i])*bmap[i] : 0.f;
    }
    // classes
    for (int i=gt; i<B*S; i+=gstep){
        const float* p = ne + i*C;
        int best = 0; float bv = p[0];
        #pragma unroll
        for (int c=1;c<C;c++){ if (p[c] > bv){ bv = p[c]; best = c; } }
        g_cls[i] = best;
    }
}

// ---------------- GEMM gs0 = zpad @ WlinT + b_lin1 ; writes g_gs and g_hin ----------------
// grid (8 ntiles, 8 mtiles), 256 thr, BM=64 BN=64 BK=16
__global__ void kgemm_gs0(const float* __restrict__ blin)
{
    __shared__ float As[16][72];
    __shared__ float Bs[16][64];
    int nt = blockIdx.x, mt = blockIdx.y;
    int t = threadIdx.x;
    int tx = t & 15, ty = t >> 4;
    int m0 = mt*64, n0 = nt*64;
    int ar = t >> 2, ak = (t & 3) << 2;
    int br = t >> 4, bc = (t & 15) << 2;
    float acc[4][4];
    #pragma unroll
    for (int i=0;i<4;i++)
        #pragma unroll
        for (int j=0;j<4;j++) acc[i][j] = 0.f;

    for (int k0=0;k0<KP;k0+=16){
        float4 av = *(const float4*)&g_zpad[m0+ar][k0+ak];
        float4 bv = *(const float4*)&g_WlinT[k0+br][n0+bc];
        As[ak+0][ar]=av.x; As[ak+1][ar]=av.y; As[ak+2][ar]=av.z; As[ak+3][ar]=av.w;
        *(float4*)&Bs[br][bc] = bv;
        __syncthreads();
        #pragma unroll
        for (int kk=0;kk<16;kk++){
            float4 a4 = *(const float4*)&As[kk][ty*4];
            float4 b4 = *(const float4*)&Bs[kk][tx*4];
            float a[4] = {a4.x,a4.y,a4.z,a4.w};
            float b[4] = {b4.x,b4.y,b4.z,b4.w};
            #pragma unroll
            for (int i=0;i<4;i++)
                #pragma unroll
                for (int j=0;j<4;j++) acc[i][j] += a[i]*b[j];
        }
        __syncthreads();
    }
    #pragma unroll
    for (int i=0;i<4;i++){
        int m = m0 + ty*4 + i;
        #pragma unroll
        for (int j=0;j<4;j++){
            int h = n0 + tx*4 + j;
            float v = (h<H) ? acc[i][j] + blin[h] : 0.f;
            g_gs[m][h] = v;
            g_hin[m][h] = v;
        }
    }
}

// ---------------- K1: GM = gs @ WcatT, epilogue h_in ----------------
// grid (16 ntiles, 8 mtiles), 256 thr, BM=64 BN=64 BK=16
__global__ void kgemm1(const float* __restrict__ dep, const float* __restrict__ bgate,
                       const float* __restrict__ bmap, int idx)
{
    __shared__ float As[16][72];
    __shared__ float Bs[16][64];
    int nt = blockIdx.x, mt = blockIdx.y;
    int t = threadIdx.x;
    int tx = t & 15, ty = t >> 4;
    int m0 = mt*64, n0 = nt*64;
    int ar = t >> 2, ak = (t & 3) << 2;
    int br = t >> 4, bc = (t & 15) << 2;
    float acc[4][4];
    #pragma unroll
    for (int i=0;i<4;i++)
        #pragma unroll
        for (int j=0;j<4;j++) acc[i][j] = 0.f;

    for (int k0=0;k0<KP;k0+=16){
        float4 av = *(const float4*)&g_gs[m0+ar][k0+ak];
        float4 bv = *(const float4*)&g_WcatT[k0+br][n0+bc];
        As[ak+0][ar]=av.x; As[ak+1][ar]=av.y; As[ak+2][ar]=av.z; As[ak+3][ar]=av.w;
        *(float4*)&Bs[br][bc] = bv;
        __syncthreads();
        #pragma unroll
        for (int kk=0;kk<16;kk++){
            float4 a4 = *(const float4*)&As[kk][ty*4];
            float4 b4 = *(const float4*)&Bs[kk][tx*4];
            float a[4] = {a4.x,a4.y,a4.z,a4.w};
            float b[4] = {b4.x,b4.y,b4.z,b4.w};
            #pragma unroll
            for (int i=0;i<4;i++)
                #pragma unroll
                for (int j=0;j<4;j++) acc[i][j] += a[i]*b[j];
        }
        __syncthreads();
    }
    int hbase = (n0>>1) + tx*2;
    #pragma unroll
    for (int i=0;i<4;i++){
        int m = m0 + ty*4 + i;
        float rb = dep[m*(S*S) + idx*S + (idx-1)];
        #pragma unroll
        for (int p=0;p<2;p++){
            int h = hbase + p;
            float val;
            if (h < H){
                float f0 = g_f0[h];
                float fv;
                if (rb != 0.f){
                    float G = acc[i][2*p], M = acc[i][2*p+1];
                    fv = sigm(G + bgate[h]) * (M + bmap[h]);
                } else {
                    fv = f0;
                }
                val = 15.f*f0 + fv;
            } else val = 0.f;
            g_hin[m][h] = val;
        }
    }
}

// ---------------- K2: gh = h_in @ Whh3T, GRU epilogue -> g_gs ----------------
// grid (32 ntiles, 8 mtiles), 256 thr, BM=64 BN=48 BK=16 (each tx owns 1 h = 3 cols)
__global__ void kgemm2(const float* __restrict__ Wih, const float* __restrict__ bih,
                       const float* __restrict__ bhh, int idx)
{
    __shared__ float As[16][72];
    __shared__ float Bs[16][48];
    int nt = blockIdx.x, mt = blockIdx.y;
    int t = threadIdx.x;
    int tx = t & 15, ty = t >> 4;
    int m0 = mt*64, n0 = nt*48;
    int ar = t >> 2, ak = (t & 3) << 2;
    float acc[4][3];
    #pragma unroll
    for (int i=0;i<4;i++)
        #pragma unroll
        for (int j=0;j<3;j++) acc[i][j] = 0.f;

    for (int k0=0;k0<KP;k0+=16){
        float4 av = *(const float4*)&g_hin[m0+ar][k0+ak];
        As[ak+0][ar]=av.x; As[ak+1][ar]=av.y; As[ak+2][ar]=av.z; As[ak+3][ar]=av.w;
        if (t < 192){
            int br = t/12, bc = (t%12)*4;
            float4 bv = *(const float4*)&g_Whh3T[k0+br][n0+bc];
            *(float4*)&Bs[br][bc] = bv;
        }
        __syncthreads();
        #pragma unroll
        for (int kk=0;kk<16;kk++){
            float4 a4 = *(const float4*)&As[kk][ty*4];
            float a[4] = {a4.x,a4.y,a4.z,a4.w};
            float b[3];
            b[0] = Bs[kk][tx*3+0];
            b[1] = Bs[kk][tx*3+1];
            b[2] = Bs[kk][tx*3+2];
            #pragma unroll
            for (int i=0;i<4;i++)
                #pragma unroll
                for (int j=0;j<3;j++) acc[i][j] += a[i]*b[j];
        }
        __syncthreads();
    }
    int h = nt*16 + tx;
    if (h < H){
        #pragma unroll
        for (int i=0;i<4;i++){
            int m = m0 + ty*4 + i;
            int c = g_cls[m*S + idx];
            float gh_r = acc[i][0] + bhh[h];
            float gh_z = acc[i][1] + bhh[H+h];
            float gh_n = acc[i][2] + bhh[2*H+h];
            float gi_r = Wih[(      h)*C + c] + bih[h];
            float gi_z = Wih[(H   + h)*C + c] + bih[H+h];
            float gi_n = Wih[(2*H + h)*C + c] + bih[2*H+h];
            float r = sigm(gi_r + gh_r);
            float u = sigm(gi_z + gh_z);
            float nn = tanhf(gi_n + r*gh_n);
            float hv = (1.f-u)*nn + u*g_hin[m][h];
            g_gs[m][h] = hv;
        }
    }
}

// ---------------- vertex logits + softmax -> enc output ----------------
__global__ void kvert(const float* __restrict__ Wv, const float* __restrict__ bv,
                      float* __restrict__ out, int idx)
{
    int b = blockIdx.x;
    int t = threadIdx.x;          // 224 threads
    int w = t >> 5, lane = t & 31;
    __shared__ float sl[C];
    float s = 0.f;
    for (int k=lane; k<H; k+=32) s += g_gs[b][k] * Wv[w*H + k];
    #pragma unroll
    for (int o=16;o>0;o>>=1) s += __shfl_down_sync(0xffffffffu, s, o);
    if (lane == 0) sl[w] = s + bv[w];
    __syncthreads();
    if (t == 0){
        float mx = sl[0];
        #pragma unroll
        for (int c=1;c<C;c++) mx = fmaxf(mx, sl[c]);
        float e[C]; float sum = 0.f;
        #pragma unroll
        for (int c=0;c<C;c++){ e[c] = expf(sl[c]-mx); sum += e[c]; }
        float inv = 1.f/sum;
        float* o = out + ENC_OFF + (b*S + idx)*C;
        #pragma unroll
        for (int c=0;c<C;c++) o[c] = e[c]*inv;
    }
}

// ---------------- edge dots + edge row output ----------------
__global__ void kedge(const float* __restrict__ We, const float* __restrict__ be,
                      float* __restrict__ out, int idx)
{
    int b = blockIdx.x;
    int t = threadIdx.x;          // 256 threads, 8 warps
    int w = t >> 5, lane = t & 31;
    float s1 = 0.f, s2 = 0.f;
    for (int k=t; k<H; k+=256){
        float g = g_gs[b][k];
        s1 += g * We[k];
        s2 += g * We[H + k];
    }
    #pragma unroll
    for (int o=16;o>0;o>>=1){
        s1 += __shfl_down_sync(0xffffffffu, s1, o);
        s2 += __shfl_down_sync(0xffffffffu, s2, o);
    }
    __shared__ float r1[8], r2[8];
    if (lane == 0){ r1[w] = s1; r2[w] = s2; }
    __syncthreads();
    if (t == 0){
        float a_new = 0.f, d_new = 0.f;
        #pragma unroll
        for (int i=0;i<8;i++){ a_new += r1[i]; d_new += r2[i]; }
        float bev = be[0];
        float a_old = g_aprev[b];
        float* row = out + DEP_OFF + (b*S + idx)*S;
        #pragma unroll
        for (int col=0; col<S; col++){
            float v;
            if (col >= idx) v = 0.f;
            else if (col == idx-1) v = (a_old + g_d[b][idx-1] + bev >= 0.f) ? 1.f : 0.f;
            else v = (a_new + g_d[b][col] + bev >= 0.f) ? 1.f : 0.f;
            row[col] = v;
        }
        g_d[b][idx] = d_new;
        g_aprev[b] = a_new;
    }
}

// ---------------- launch ----------------
extern "C" void kernel_launch(void* const* d_in, const int* in_sizes, int n_in,
                              void* d_out, int out_size)
{
    const float* z     = (const float*)d_in[0];
    const float* dep   = (const float*)d_in[1];
    const float* ne    = (const float*)d_in[2];
    const float* Wlin  = (const float*)d_in[3];
    const float* blin  = (const float*)d_in[4];
    const float* Wv    = (const float*)d_in[5];
    const float* bv    = (const float*)d_in[6];
    const float* We    = (const float*)d_in[7];
    const float* be    = (const float*)d_in[8];
    const float* Wg    = (const float*)d_in[9];
    const float* bgate = (const float*)d_in[10];
    const float* Wm    = (const float*)d_in[11];
    const float* bmap  = (const float*)d_in[12];
    const float* Wih   = (const float*)d_in[13];
    const float* bih   = (const float*)d_in[14];
    const float* Whh   = (const float*)d_in[15];
    const float* bhh   = (const float*)d_in[16];
    float* out = (float*)d_out;

    kinit<<<1024, 256>>>(Wg, Wm, Whh, Wlin, bgate, bmap, z, ne);
    kgemm_gs0<<<dim3(8,8), 256>>>(blin);
    for (int idx=0; idx<S; ++idx){
        kvert<<<B, 224>>>(Wv, bv, out, idx);
        if (idx >= 1) kgemm1<<<dim3(16,8), 256>>>(dep, bgate, bmap, idx);
        kgemm2<<<dim3(32,8), 256>>>(Wih, bih, bhh, idx);
        kedge<<<B, 256>>>(We, be, out, idx);
    }
    (void)in_sizes; (void)n_in; (void)out_size;
}